// round 6
// baseline (speedup 1.0000x reference)
#include <cuda_runtime.h>
#include <math.h>

#define BATCH  4
#define NPTS   8192
#define TPB    256
#define PPT    4                       // pred points per thread
#define PPB    (TPB * PPT)             // 1024 pred points per block (i-tile)
#define ITILES (NPTS / PPB)            // 8
#define JTILE  256                     // gt points per block (j-tile)
#define JTILES (NPTS / JTILE)          // 32
#define SLOTS  (BATCH * NPTS)          // 32768
#define RBLK   128

// Partial mins; every slot written exactly once per launch -> no init needed.
__device__ float g_rowp[JTILES][SLOTS];   // min over j-tile, per (b, i)
__device__ float g_colp[ITILES][SLOTS];   // min over i-tile, per (b, j)
__device__ float g_part[RBLK];

__global__ void __launch_bounds__(TPB) chamfer_fused(
    const float* __restrict__ pred, const float* __restrict__ gt)
{
    __shared__ float4   sg[JTILE];       // (-2gx, -2gy, -2gz, |g|^2)
    __shared__ unsigned cmin[JTILE];     // column mins (float-as-uint, >=0)

    int bid = blockIdx.x;
    int jt = bid % JTILES;  bid /= JTILES;
    int it = bid % ITILES;  bid /= ITILES;
    int b  = bid;

    const float* P = pred + (size_t)b * 3 * NPTS;
    const float* G = gt   + (size_t)b * 3 * NPTS;

    // Stage gt tile (256 threads, 256 j's: one each)
    {
        int j = jt * JTILE + threadIdx.x;
        float gx = G[j];
        float gy = G[NPTS + j];
        float gz = G[2 * NPTS + j];
        sg[threadIdx.x] = make_float4(-2.0f * gx, -2.0f * gy, -2.0f * gz,
                                      fmaf(gx, gx, fmaf(gy, gy, gz * gz)));
        cmin[threadIdx.x] = 0x7f800000u;  // +inf
    }
    __syncthreads();

    float px[PPT], py[PPT], pz[PPT], psq[PPT], mn[PPT];
    int i0 = it * PPB + threadIdx.x;
    #pragma unroll
    for (int p = 0; p < PPT; p++) {
        int i = i0 + p * TPB;
        px[p] = P[i];
        py[p] = P[NPTS + i];
        pz[p] = P[2 * NPTS + i];
        psq[p] = fmaf(px[p], px[p], fmaf(py[p], py[p], pz[p] * pz[p]));
        mn[p] = 3.0e38f;
    }

    int lane = threadIdx.x & 31;

    #pragma unroll 4
    for (int j = 0; j < JTILE; j++) {
        float4 g = sg[j];                 // LDS.128 broadcast
        float dt = 3.0e38f;
        #pragma unroll
        for (int p = 0; p < PPT; p++) {
            float acc = fmaf(pz[p], g.z, g.w);     // |g|^2 - 2 p.g
            acc = fmaf(py[p], g.y, acc);
            acc = fmaf(px[p], g.x, acc);
            mn[p] = fminf(mn[p], acc);             // row min (psq folded later)
            dt = fminf(dt, acc + psq[p]);          // column candidate needs psq_i
        }
        dt = fmaxf(dt, 0.0f);                      // clamp -> uint order valid
        unsigned u = __reduce_min_sync(0xffffffffu, __float_as_uint(dt));
        if (lane == 0) atomicMin(&cmin[j], u);
    }
    __syncthreads();

    // Row partials: unique writer per (jt, b, i)
    float* rp = &g_rowp[jt][b * NPTS];
    #pragma unroll
    for (int p = 0; p < PPT; p++)
        rp[i0 + p * TPB] = fmaxf(psq[p] + mn[p], 0.0f);

    // Column partials: unique writer per (it, b, j)
    g_colp[it][b * NPTS + jt * JTILE + threadIdx.x] =
        __uint_as_float(cmin[threadIdx.x]);
}

__global__ void __launch_bounds__(TPB) reduce_kernel() {
    __shared__ float ssum[TPB];
    int gid = blockIdx.x * TPB + threadIdx.x;   // 32768 threads, one slot each

    float rm = 3.0e38f;
    #pragma unroll
    for (int t = 0; t < JTILES; t++) rm = fminf(rm, g_rowp[t][gid]);
    float cm = 3.0e38f;
    #pragma unroll
    for (int t = 0; t < ITILES; t++) cm = fminf(cm, g_colp[t][gid]);

    float s = sqrtf(rm) + sqrtf(cm);
    ssum[threadIdx.x] = s;
    __syncthreads();
    for (int off = TPB / 2; off > 0; off >>= 1) {
        if (threadIdx.x < off) ssum[threadIdx.x] += ssum[threadIdx.x + off];
        __syncthreads();
    }
    if (threadIdx.x == 0) g_part[blockIdx.x] = ssum[0];
}

__global__ void __launch_bounds__(RBLK) final_kernel(float* __restrict__ out) {
    __shared__ float ssum[RBLK];
    int tid = threadIdx.x;
    ssum[tid] = g_part[tid];
    __syncthreads();
    for (int off = RBLK / 2; off > 0; off >>= 1) {
        if (tid < off) ssum[tid] += ssum[tid + off];
        __syncthreads();
    }
    if (tid == 0) out[0] = ssum[0] * (1.0f / (float)BATCH);
}

extern "C" void kernel_launch(void* const* d_in, const int* in_sizes, int n_in,
                              void* d_out, int out_size) {
    const float* pred = (const float*)d_in[0];
    const float* gt   = (const float*)d_in[1];
    float* out = (float*)d_out;
    (void)in_sizes; (void)n_in; (void)out_size;

    // grid: 32 j-tiles * 8 i-tiles * 4 batches = 1024 blocks (single pass, both mins)
    chamfer_fused<<<JTILES * ITILES * BATCH, TPB>>>(pred, gt);
    reduce_kernel<<<RBLK, TPB>>>();      // 32768 threads: one (b, idx) slot each
    final_kernel<<<1, RBLK>>>(out);
}